// round 10
// baseline (speedup 1.0000x reference)
#include <cuda_runtime.h>
#include <cuda_fp16.h>
#include <cuda_bf16.h>

// NGP geodesic-weighted multi-level grid interpolation — fp16 quads,
// level-3 table in shared memory, persistent 512-thread CTAs.
//
// Gather cost model (validated R8/R9): scattered gathers cost ~1 L1tex
// wavefront per 128-bit transaction per lane. fp16 quads make each level one
// LDG.128. This round removes the level-3 LDG entirely: its quad table is
// 4192 x 16B = 67KB -> shared memory (random LDS.128 ~ 8-12 cyc/warp vs 32
// wavefronts/warp for the LDG it replaces). Persistent grid (444 CTAs) keeps
// smem fill at 30MB total; 512-thr CTAs give 3 CTAs/SM = 48 warps resident.

#define TABLE_SIZE (721 * 1441)

// Reachable quad ranges per level (bl0max*W + bl1max + margin):
#define NQ0 261008
#define NQ1 65712
#define NQ2 16656
#define NQ3 4192
#define QOFF0 0
#define QOFF1 (NQ0)
#define QOFF2 (NQ0 + NQ1)
#define QOFF3 (NQ0 + NQ1 + NQ2)
#define NQUADS (NQ0 + NQ1 + NQ2 + NQ3)

#define BM0 (-90.25f)
#define BM1 (-0.25f)
#define BX0 (90.25f)
#define BX1 (360.25f)
#define RAD 0.017453292519943295f
#define SCALE_UP   8192.0f          // 2^13, exact
#define SCALE_DOWN (1.0f / 8192.0f) // exact

// fp16 quad: {e00x,e00y,e01x,e01y,e10x,e10y,e11x,e11y} = 16B. Total 5.56 MB.
__device__ __align__(16) __half2 g_quads[4 * NQUADS];

__global__ __launch_bounds__(256)
void build_quads(const float* __restrict__ emb)
{
    int t = blockIdx.x * blockDim.x + threadIdx.x;
    if (t >= NQUADS) return;
    int level, j, W;
    if (t < QOFF1)      { level = 0; j = t;         W = 1440; }
    else if (t < QOFF2) { level = 1; j = t - QOFF1; W = 720;  }
    else if (t < QOFF3) { level = 2; j = t - QOFF2; W = 360;  }
    else                { level = 3; j = t - QOFF3; W = 180;  }
    const float2* tab = reinterpret_cast<const float2*>(emb) + level * TABLE_SIZE;
    float2 a = __ldg(tab + j);        // e00
    float2 b = __ldg(tab + j + 1);    // e01
    float2 c = __ldg(tab + j + W);    // e10
    float2 d = __ldg(tab + j + W + 1);// e11
    __half2* q = &g_quads[4 * t];
    q[0] = __floats2half2_rn(a.x * SCALE_UP, a.y * SCALE_UP);
    q[1] = __floats2half2_rn(b.x * SCALE_UP, b.y * SCALE_UP);
    q[2] = __floats2half2_rn(c.x * SCALE_UP, c.y * SCALE_UP);
    q[3] = __floats2half2_rn(d.x * SCALE_UP, d.y * SCALE_UP);
}

#define TPB 512
#define NCTA (148 * 3)

__global__ __launch_bounds__(TPB, 3)
void interp_kernel(const float* __restrict__ x,
                   float* __restrict__ out,
                   int B)
{
    extern __shared__ uint4 s3[];   // level-3 quads: NQ3 * 16B = 67,072 B

    const uint4* qt = reinterpret_cast<const uint4*>(g_quads);
    for (int j = threadIdx.x; j < NQ3; j += TPB)
        s3[j] = __ldg(qt + QOFF3 + j);
    __syncthreads();

    const int stride = gridDim.x * TPB;
    for (int b = blockIdx.x * TPB + threadIdx.x; b < B; b += stride) {
        float2 p  = reinterpret_cast<const float2*>(x)[b];
        float lat = p.x, lon = p.y;
        float clat = fminf(fmaxf(lat, BM0), BX0);
        float clon = fminf(fmaxf(lon, BM1), BX1);

        // ---- indices for all 4 levels ----
        int bl0a[4], bl1a[4];
#pragma unroll
        for (int i = 0; i < 4; i++) {
            const float inv = 1.0f / (float)(1 << i);
            bl0a[i] = (int)floorf((clat - BM0) * inv);
            bl1a[i] = (int)floorf((clon - BM1) * inv);
        }

        // ---- 3 scattered 128-bit gathers (MLP=3) + 1 shared-mem read ----
        uint4 qa[4];
        qa[0] = __ldg(qt + (QOFF0 + bl0a[0] * 1440 + bl1a[0]));
        qa[1] = __ldg(qt + (QOFF1 + bl0a[1] *  720 + bl1a[1]));
        qa[2] = __ldg(qt + (QOFF2 + bl0a[2] *  360 + bl1a[2]));
        qa[3] = s3[bl0a[3] * 180 + bl1a[3]];

        // ---- weights + bilinear, matching reference ----
        float res[8];
#pragma unroll
        for (int i = 0; i < 4; i++) {
            const float gs  = (float)(1 << i);
            const float inv = 1.0f / gs;

            float gmin0 = (float)bl0a[i] * gs + BM0;
            float gmin1 = (float)bl1a[i] * gs + BM1;

            // wlat: geodesic along constant lon == |dlat|/gs (UNCLIPPED lat).
            float wlat = (lat - gmin0) * inv;

            // wlon: asin(|c| sin((gmax1-lon)r/2)) / asin(|c| sin(gs r/2)),
            // args <= 0.07 rad -> 2-term Taylor, rel err ~2e-7 (tol 1e-3).
            float dlon = (gmin1 + gs) - lon;
            float c    = fabsf(__cosf(gmin0 * RAD));
            float zn = dlon * (RAD * 0.5f);
            float zd = gs   * (RAD * 0.5f);
            float sn = zn - zn * zn * zn * (1.0f / 6.0f);
            float sd = zd - zd * zd * zd * (1.0f / 6.0f);
            float tn = c * sn, td = c * sd;
            float tn2 = tn * tn, td2 = td * td;
            float an = tn * (1.0f + tn2 * (1.0f / 6.0f) + tn2 * tn2 * (3.0f / 40.0f));
            float ad = td * (1.0f + td2 * (1.0f / 6.0f) + td2 * td2 * (3.0f / 40.0f));
            float wlon = an / ad;

            float2 e00 = __half22float2(*reinterpret_cast<const __half2*>(&qa[i].x));
            float2 e01 = __half22float2(*reinterpret_cast<const __half2*>(&qa[i].y));
            float2 e10 = __half22float2(*reinterpret_cast<const __half2*>(&qa[i].z));
            float2 e11 = __half22float2(*reinterpret_cast<const __half2*>(&qa[i].w));

            float c0x = fmaf(e10.x - e00.x, wlat, e00.x);
            float c0y = fmaf(e10.y - e00.y, wlat, e00.y);
            float c1x = fmaf(e11.x - e01.x, wlat, e01.x);
            float c1y = fmaf(e11.y - e01.y, wlat, e01.y);

            res[2 * i + 0] = fmaf(c1x - c0x, wlon, c0x) * SCALE_DOWN;
            res[2 * i + 1] = fmaf(c1y - c0y, wlon, c0y) * SCALE_DOWN;
        }

        float4* o = reinterpret_cast<float4*>(out) + (size_t)b * 2;
        o[0] = make_float4(res[0], res[1], res[2], res[3]);
        o[1] = make_float4(res[4], res[5], res[6], res[7]);
    }
}

extern "C" void kernel_launch(void* const* d_in, const int* in_sizes, int n_in,
                              void* d_out, int out_size)
{
    const float* x   = (const float*)d_in[0];
    const float* emb = (const float*)d_in[1];
    float*       out = (float*)d_out;

    int B = in_sizes[0] / 2;
    const int SMEM = NQ3 * sizeof(uint4);   // 67,072 B

    static bool attr_set = false;
    if (!attr_set) {
        cudaFuncSetAttribute(interp_kernel,
                             cudaFuncAttributeMaxDynamicSharedMemorySize, SMEM);
        attr_set = true;
    }

    build_quads<<<(NQUADS + 255) / 256, 256>>>(emb);
    interp_kernel<<<NCTA, TPB, SMEM>>>(x, out, B);
}

// round 11
// speedup vs baseline: 1.4706x; 1.4706x over previous
#include <cuda_runtime.h>
#include <cuda_fp16.h>
#include <cuda_bf16.h>

// NGP geodesic-weighted multi-level grid interpolation — fp16 quads,
// 2 points/thread, full grid (persistent loops starve the L1 queue: R7, R10).
//
// Cost model (validated R8/R9): scattered gathers cost ~1 L1tex wavefront per
// 128-bit transaction per lane; fp16 quads = one LDG.128 per level per point.
// R9 ran at 85% of that floor (latency-exposed, issue=46%). This round doubles
// per-thread MLP: both points' indices computed first, all 8 gathers issued
// back-to-back, then the math. x read becomes one coalesced float4/thread,
// output 64B contiguous/thread.

#define TABLE_SIZE (721 * 1441)

// Reachable quad ranges per level (bl0max*W + bl1max + margin):
#define NQ0 261008
#define NQ1 65712
#define NQ2 16656
#define NQ3 4192
#define QOFF0 0
#define QOFF1 (NQ0)
#define QOFF2 (NQ0 + NQ1)
#define QOFF3 (NQ0 + NQ1 + NQ2)
#define NQUADS (NQ0 + NQ1 + NQ2 + NQ3)

#define BM0 (-90.25f)
#define BM1 (-0.25f)
#define BX0 (90.25f)
#define BX1 (360.25f)
#define RAD 0.017453292519943295f
#define SCALE_UP   8192.0f          // 2^13, exact
#define SCALE_DOWN (1.0f / 8192.0f) // exact

// fp16 quad: {e00x,e00y,e01x,e01y,e10x,e10y,e11x,e11y} = 16B. Total 5.56 MB.
__device__ __align__(16) __half2 g_quads[4 * NQUADS];

__global__ __launch_bounds__(256)
void build_quads(const float* __restrict__ emb)
{
    int t = blockIdx.x * blockDim.x + threadIdx.x;
    if (t >= NQUADS) return;
    int level, j, W;
    if (t < QOFF1)      { level = 0; j = t;         W = 1440; }
    else if (t < QOFF2) { level = 1; j = t - QOFF1; W = 720;  }
    else if (t < QOFF3) { level = 2; j = t - QOFF2; W = 360;  }
    else                { level = 3; j = t - QOFF3; W = 180;  }
    const float2* tab = reinterpret_cast<const float2*>(emb) + level * TABLE_SIZE;
    float2 a = __ldg(tab + j);        // e00
    float2 b = __ldg(tab + j + 1);    // e01
    float2 c = __ldg(tab + j + W);    // e10
    float2 d = __ldg(tab + j + W + 1);// e11
    __half2* q = &g_quads[4 * t];
    q[0] = __floats2half2_rn(a.x * SCALE_UP, a.y * SCALE_UP);
    q[1] = __floats2half2_rn(b.x * SCALE_UP, b.y * SCALE_UP);
    q[2] = __floats2half2_rn(c.x * SCALE_UP, c.y * SCALE_UP);
    q[3] = __floats2half2_rn(d.x * SCALE_UP, d.y * SCALE_UP);
}

// Per-point cell indices + cell minima. args >= 0 so __float2int_rd == floor.
__device__ __forceinline__ void cell_ids(float clat, float clon,
                                         int idx[4], float g0[4], float g1[4])
{
#pragma unroll
    for (int i = 0; i < 4; i++) {
        const float gs  = (float)(1 << i);
        const float inv = 1.0f / gs;
        int bl0 = __float2int_rd((clat - BM0) * inv);
        int bl1 = __float2int_rd((clon - BM1) * inv);
        g0[i] = (float)bl0 * gs + BM0;
        g1[i] = (float)bl1 * gs + BM1;
        const int W    = 1440 >> i;
        const int offs[4] = {QOFF0, QOFF1, QOFF2, QOFF3};
        idx[i] = offs[i] + bl0 * W + bl1;
    }
}

__device__ __forceinline__ void point_math(float lat, float lon,
                                           const float g0[4], const float g1[4],
                                           const uint4 qa[4], float res[8])
{
#pragma unroll
    for (int i = 0; i < 4; i++) {
        const float gs  = (float)(1 << i);
        const float inv = 1.0f / gs;

        // wlat: geodesic along constant lon == |dlat|/gs (UNCLIPPED lat).
        float wlat = (lat - g0[i]) * inv;

        // wlon: asin(|c| sin((gmax1-lon)r/2)) / asin(|c| sin(gs r/2)),
        // args <= 0.07 rad -> 2-term Taylor, rel err ~2e-7 (tol 1e-3).
        float dlon = (g1[i] + gs) - lon;
        float c    = fabsf(__cosf(g0[i] * RAD));
        float zn = dlon * (RAD * 0.5f);
        float zd = gs   * (RAD * 0.5f);
        float sn = zn - zn * zn * zn * (1.0f / 6.0f);
        float sd = zd - zd * zd * zd * (1.0f / 6.0f);
        float tn = c * sn, td = c * sd;
        float tn2 = tn * tn, td2 = td * td;
        float an = tn * (1.0f + tn2 * (1.0f / 6.0f) + tn2 * tn2 * (3.0f / 40.0f));
        float ad = td * (1.0f + td2 * (1.0f / 6.0f) + td2 * td2 * (3.0f / 40.0f));
        float wlon = an / ad;

        float2 e00 = __half22float2(*reinterpret_cast<const __half2*>(&qa[i].x));
        float2 e01 = __half22float2(*reinterpret_cast<const __half2*>(&qa[i].y));
        float2 e10 = __half22float2(*reinterpret_cast<const __half2*>(&qa[i].z));
        float2 e11 = __half22float2(*reinterpret_cast<const __half2*>(&qa[i].w));

        float c0x = fmaf(e10.x - e00.x, wlat, e00.x);
        float c0y = fmaf(e10.y - e00.y, wlat, e00.y);
        float c1x = fmaf(e11.x - e01.x, wlat, e01.x);
        float c1y = fmaf(e11.y - e01.y, wlat, e01.y);

        res[2 * i + 0] = fmaf(c1x - c0x, wlon, c0x) * SCALE_DOWN;
        res[2 * i + 1] = fmaf(c1y - c0y, wlon, c0y) * SCALE_DOWN;
    }
}

__global__ __launch_bounds__(256, 4)
void interp_kernel(const float* __restrict__ x,
                   float* __restrict__ out,
                   int B)
{
    int t  = blockIdx.x * blockDim.x + threadIdx.x;
    int b0 = 2 * t;
    if (b0 >= B) return;
    bool has2 = (b0 + 1 < B);

    // Coalesced point read: two adjacent float2 = one float4.
    float lat0, lon0, lat1, lon1;
    if (has2) {
        float4 pp = __ldg(reinterpret_cast<const float4*>(x) + t);
        lat0 = pp.x; lon0 = pp.y; lat1 = pp.z; lon1 = pp.w;
    } else {
        float2 pp = __ldg(reinterpret_cast<const float2*>(x) + b0);
        lat0 = pp.x; lon0 = pp.y; lat1 = pp.x; lon1 = pp.y;
    }

    float clat0 = fminf(fmaxf(lat0, BM0), BX0);
    float clon0 = fminf(fmaxf(lon0, BM1), BX1);
    float clat1 = fminf(fmaxf(lat1, BM0), BX0);
    float clon1 = fminf(fmaxf(lon1, BM1), BX1);

    int   idxA[4], idxB[4];
    float g0A[4], g1A[4], g0B[4], g1B[4];
    cell_ids(clat0, clon0, idxA, g0A, g1A);
    cell_ids(clat1, clon1, idxB, g0B, g1B);

    // All 8 scattered 128-bit gathers issued back-to-back (MLP=8).
    const uint4* qt = reinterpret_cast<const uint4*>(g_quads);
    uint4 qaA[4], qaB[4];
#pragma unroll
    for (int i = 0; i < 4; i++) qaA[i] = __ldg(qt + idxA[i]);
#pragma unroll
    for (int i = 0; i < 4; i++) qaB[i] = __ldg(qt + idxB[i]);

    float resA[8], resB[8];
    point_math(lat0, lon0, g0A, g1A, qaA, resA);
    point_math(lat1, lon1, g0B, g1B, qaB, resB);

    float4* o = reinterpret_cast<float4*>(out) + (size_t)b0 * 2;
    o[0] = make_float4(resA[0], resA[1], resA[2], resA[3]);
    o[1] = make_float4(resA[4], resA[5], resA[6], resA[7]);
    if (has2) {
        o[2] = make_float4(resB[0], resB[1], resB[2], resB[3]);
        o[3] = make_float4(resB[4], resB[5], resB[6], resB[7]);
    }
}

extern "C" void kernel_launch(void* const* d_in, const int* in_sizes, int n_in,
                              void* d_out, int out_size)
{
    const float* x   = (const float*)d_in[0];
    const float* emb = (const float*)d_in[1];
    float*       out = (float*)d_out;

    int B = in_sizes[0] / 2;
    const int T = 256;

    build_quads<<<(NQUADS + T - 1) / T, T>>>(emb);

    int nthreads = (B + 1) / 2;
    interp_kernel<<<(nthreads + T - 1) / T, T>>>(x, out, B);
}

// round 12
// speedup vs baseline: 1.5456x; 1.0510x over previous
#include <cuda_runtime.h>
#include <cuda_fp16.h>
#include <cuda_bf16.h>

// NGP geodesic-weighted multi-level grid interpolation — fp16 quads,
// 1 point/thread, occupancy-tuned (6 CTAs/SM).
//
// Cost model (validated R8-R11): scattered gathers cost ~1 L1tex wavefront per
// 128-bit transaction per lane -> fp16 quads give one LDG.128 per level
// (4.3 wf/pt incl. I/O; service floor ~31us). R9 ran at 80% of floor with
// occupancy self-capped at 40 warps by launch_bounds(256,5). This round:
// 6 CTAs/SM (48 warps), __float2int_rd, weight math hoisted ahead of the
// gather-consume point. 2pt/thread (R11) and persistent grids (R7/R10) both
// regressed; full grid + 1pt/thread + max warps is the validated shape.

#define TABLE_SIZE (721 * 1441)

// Reachable quad ranges per level (bl0max*W + bl1max + margin):
#define NQ0 261008
#define NQ1 65712
#define NQ2 16656
#define NQ3 4192
#define QOFF0 0
#define QOFF1 (NQ0)
#define QOFF2 (NQ0 + NQ1)
#define QOFF3 (NQ0 + NQ1 + NQ2)
#define NQUADS (NQ0 + NQ1 + NQ2 + NQ3)

#define BM0 (-90.25f)
#define BM1 (-0.25f)
#define BX0 (90.25f)
#define BX1 (360.25f)
#define RAD 0.017453292519943295f
#define SCALE_UP   8192.0f          // 2^13, exact
#define SCALE_DOWN (1.0f / 8192.0f) // exact

// fp16 quad: {e00x,e00y,e01x,e01y,e10x,e10y,e11x,e11y} = 16B. Total 5.56 MB.
__device__ __align__(16) __half2 g_quads[4 * NQUADS];

__global__ __launch_bounds__(256)
void build_quads(const float* __restrict__ emb)
{
    int t = blockIdx.x * blockDim.x + threadIdx.x;
    if (t >= NQUADS) return;
    int level, j, W;
    if (t < QOFF1)      { level = 0; j = t;         W = 1440; }
    else if (t < QOFF2) { level = 1; j = t - QOFF1; W = 720;  }
    else if (t < QOFF3) { level = 2; j = t - QOFF2; W = 360;  }
    else                { level = 3; j = t - QOFF3; W = 180;  }
    const float2* tab = reinterpret_cast<const float2*>(emb) + level * TABLE_SIZE;
    float2 a = __ldg(tab + j);        // e00
    float2 b = __ldg(tab + j + 1);    // e01
    float2 c = __ldg(tab + j + W);    // e10
    float2 d = __ldg(tab + j + W + 1);// e11
    __half2* q = &g_quads[4 * t];
    q[0] = __floats2half2_rn(a.x * SCALE_UP, a.y * SCALE_UP);
    q[1] = __floats2half2_rn(b.x * SCALE_UP, b.y * SCALE_UP);
    q[2] = __floats2half2_rn(c.x * SCALE_UP, c.y * SCALE_UP);
    q[3] = __floats2half2_rn(d.x * SCALE_UP, d.y * SCALE_UP);
}

__global__ __launch_bounds__(256, 6)
void interp_kernel(const float* __restrict__ x,
                   float* __restrict__ out,
                   int B)
{
    int b = blockIdx.x * blockDim.x + threadIdx.x;
    if (b >= B) return;

    float2 p  = __ldg(reinterpret_cast<const float2*>(x) + b);
    float lat = p.x, lon = p.y;
    float clat = fminf(fmaxf(lat, BM0), BX0);
    float clon = fminf(fmaxf(lon, BM1), BX1);

    // ---- indices for all 4 levels (args >= 0: __float2int_rd == floor) ----
    int bl0a[4], bl1a[4];
#pragma unroll
    for (int i = 0; i < 4; i++) {
        const float inv = 1.0f / (float)(1 << i);
        bl0a[i] = __float2int_rd((clat - BM0) * inv);
        bl1a[i] = __float2int_rd((clon - BM1) * inv);
    }

    // ---- 4 scattered 128-bit gathers, back-to-back (MLP=4) ----
    const uint4* qt = reinterpret_cast<const uint4*>(g_quads);
    uint4 qa[4];
    qa[0] = __ldg(qt + (QOFF0 + bl0a[0] * 1440 + bl1a[0]));
    qa[1] = __ldg(qt + (QOFF1 + bl0a[1] *  720 + bl1a[1]));
    qa[2] = __ldg(qt + (QOFF2 + bl0a[2] *  360 + bl1a[2]));
    qa[3] = __ldg(qt + (QOFF3 + bl0a[3] *  180 + bl1a[3]));

    // ---- weights first (independent of gathers; hides load latency) ----
    float wlat[4], wlon[4];
#pragma unroll
    for (int i = 0; i < 4; i++) {
        const float gs  = (float)(1 << i);
        const float inv = 1.0f / gs;

        float gmin0 = (float)bl0a[i] * gs + BM0;
        float gmin1 = (float)bl1a[i] * gs + BM1;

        // wlat: geodesic along constant lon == |dlat|/gs (UNCLIPPED lat).
        wlat[i] = (lat - gmin0) * inv;

        // wlon: asin(|c| sin((gmax1-lon)r/2)) / asin(|c| sin(gs r/2)),
        // args <= 0.07 rad -> 2-term Taylor, rel err ~2e-7 (tol 1e-3).
        float dlon = (gmin1 + gs) - lon;
        float c    = fabsf(__cosf(gmin0 * RAD));
        float zn = dlon * (RAD * 0.5f);
        float zd = gs   * (RAD * 0.5f);
        float sn = zn - zn * zn * zn * (1.0f / 6.0f);
        float sd = zd - zd * zd * zd * (1.0f / 6.0f);
        float tn = c * sn, td = c * sd;
        float tn2 = tn * tn, td2 = td * td;
        float an = tn * (1.0f + tn2 * (1.0f / 6.0f) + tn2 * tn2 * (3.0f / 40.0f));
        float ad = td * (1.0f + td2 * (1.0f / 6.0f) + td2 * td2 * (3.0f / 40.0f));
        wlon[i] = an / ad;
    }

    // ---- consume gathers: bilinear combine ----
    float res[8];
#pragma unroll
    for (int i = 0; i < 4; i++) {
        float2 e00 = __half22float2(*reinterpret_cast<const __half2*>(&qa[i].x));
        float2 e01 = __half22float2(*reinterpret_cast<const __half2*>(&qa[i].y));
        float2 e10 = __half22float2(*reinterpret_cast<const __half2*>(&qa[i].z));
        float2 e11 = __half22float2(*reinterpret_cast<const __half2*>(&qa[i].w));

        float c0x = fmaf(e10.x - e00.x, wlat[i], e00.x);
        float c0y = fmaf(e10.y - e00.y, wlat[i], e00.y);
        float c1x = fmaf(e11.x - e01.x, wlat[i], e01.x);
        float c1y = fmaf(e11.y - e01.y, wlat[i], e01.y);

        res[2 * i + 0] = fmaf(c1x - c0x, wlon[i], c0x) * SCALE_DOWN;
        res[2 * i + 1] = fmaf(c1y - c0y, wlon[i], c0y) * SCALE_DOWN;
    }

    float4* o = reinterpret_cast<float4*>(out) + (size_t)b * 2;
    o[0] = make_float4(res[0], res[1], res[2], res[3]);
    o[1] = make_float4(res[4], res[5], res[6], res[7]);
}

extern "C" void kernel_launch(void* const* d_in, const int* in_sizes, int n_in,
                              void* d_out, int out_size)
{
    const float* x   = (const float*)d_in[0];
    const float* emb = (const float*)d_in[1];
    float*       out = (float*)d_out;

    int B = in_sizes[0] / 2;
    const int T = 256;

    build_quads<<<(NQUADS + T - 1) / T, T>>>(emb);
    interp_kernel<<<(B + T - 1) / T, T>>>(x, out, B);
}